// round 4
// baseline (speedup 1.0000x reference)
#include <cuda_runtime.h>
#include <cstdint>

// Problem: states [B=64, L=4096, D=256] f32; w [256] f32; bias scalar f32.
// out[b,l] = reverse_cumsum_l( dot(states[b,l,:], w) + bias )
//
// Fused single kernel: each 256-thread block computes 8 dot products
// (1 warp per row). Blocks are grouped per batch row (512 blocks / batch).
// The last-arriving block of each batch performs the in-place reverse
// cumulative sum for that row (values are L2-resident). This removes the
// serialized second-kernel launch (~5us) from the critical path.

static constexpr int B = 64;
static constexpr int L = 4096;
static constexpr int D = 256;                 // 64 float4 per row
static constexpr int ROWS = B * L;            // 262144
static constexpr int ROWS_PER_BLOCK = 8;      // 8 warps of 256 threads
static constexpr int BLOCKS_PER_BATCH = L / ROWS_PER_BLOCK;  // 512

// per-batch arrival counters; zero at load, reset by the scanning block so
// every graph replay starts from 0. No device allocation.
__device__ int g_counters[B];

__global__ void __launch_bounds__(256)
fused_kernel(const float4* __restrict__ states4,
             const float4* __restrict__ w4,
             const float*  __restrict__ bias,
             float* __restrict__ out)
{
    const int lane = threadIdx.x & 31;
    const int wid  = threadIdx.x >> 5;
    const int b    = blockIdx.x / BLOCKS_PER_BATCH;
    const int gwarp = blockIdx.x * ROWS_PER_BLOCK + wid;   // global row index

    // ---- phase 1: dot product, 1 warp per (b,l) row ----
    {
        const float4* row = states4 + (size_t)gwarp * (D / 4);
        float4 a0 = row[lane];
        float4 a1 = row[lane + 32];
        float4 w0 = __ldg(&w4[lane]);
        float4 w1 = __ldg(&w4[lane + 32]);

        float s = a0.x * w0.x + a0.y * w0.y + a0.z * w0.z + a0.w * w0.w
                + a1.x * w1.x + a1.y * w1.y + a1.z * w1.z + a1.w * w1.w;

        #pragma unroll
        for (int off = 16; off > 0; off >>= 1)
            s += __shfl_xor_sync(0xFFFFFFFFu, s, off);

        if (lane == 0)
            out[gwarp] = s + __ldg(bias);
    }

    // ---- phase 2: last block of this batch does the reverse cumsum ----
    __threadfence();            // release our 8 values to L2
    __syncthreads();

    __shared__ int is_last;
    if (threadIdx.x == 0) {
        int old = atomicAdd(&g_counters[b], 1);
        is_last = (old == BLOCKS_PER_BATCH - 1);
    }
    __syncthreads();
    if (!is_last) return;

    __threadfence();            // acquire: other blocks' values visible via L2

    // 256 threads, each owns 16 contiguous elements of out[b, :]
    constexpr int PER = L / 256;               // 16
    const float* rowr = out + (size_t)b * L;
    float*       roww = out + (size_t)b * L;
    const int t    = threadIdx.x;
    const int base = t * PER;

    float v[PER];
    #pragma unroll
    for (int i = 0; i < PER / 4; i++) {
        float4 x = __ldcg(reinterpret_cast<const float4*>(rowr + base) + i);
        v[4*i+0] = x.x; v[4*i+1] = x.y; v[4*i+2] = x.z; v[4*i+3] = x.w;
    }

    float total = 0.f;
    #pragma unroll
    for (int k = 0; k < PER; k++) total += v[k];

    // inclusive SUFFIX scan of totals within warp (lane i gets sum of lanes >= i)
    float s = total;
    #pragma unroll
    for (int off = 1; off < 32; off <<= 1) {
        float n = __shfl_down_sync(0xFFFFFFFFu, s, off);
        if (lane < 32 - off) s += n;
    }

    __shared__ float warp_tot[8];
    float wsum = __shfl_sync(0xFFFFFFFFu, s, 0);   // warp's full sum
    if (lane == 0) warp_tot[wid] = wsum;
    __syncthreads();

    float warp_off = 0.f;
    #pragma unroll
    for (int w = 0; w < 8; w++)
        if (w > wid) warp_off += warp_tot[w];

    // exclusive suffix for this thread: everything strictly after its chunk
    float offset = warp_off + (s - total);

    // within-chunk reverse cumsum
    float acc = offset;
    #pragma unroll
    for (int k = PER - 1; k >= 0; k--) {
        acc += v[k];
        v[k] = acc;
    }

    #pragma unroll
    for (int i = 0; i < PER / 4; i++) {
        float4 x = make_float4(v[4*i+0], v[4*i+1], v[4*i+2], v[4*i+3]);
        reinterpret_cast<float4*>(roww + base)[i] = x;
    }

    // reset counter for next graph replay
    if (threadIdx.x == 0) g_counters[b] = 0;
}

extern "C" void kernel_launch(void* const* d_in, const int* in_sizes, int n_in,
                              void* d_out, int out_size)
{
    const float4* states4 = (const float4*)d_in[0];
    const float4* w4      = (const float4*)d_in[1];
    const float*  bias    = (const float*)d_in[2];
    float* out = (float*)d_out;

    fused_kernel<<<ROWS / ROWS_PER_BLOCK, 256>>>(states4, w4, bias, out);
}

// round 5
// speedup vs baseline: 1.4765x; 1.4765x over previous
#include <cuda_runtime.h>
#include <cstdint>

// Problem: states [B=64, L=4096, D=256] f32; w [256] f32; bias scalar f32.
// out[b,l] = reverse_cumsum_l( dot(states[b,l,:], w) + bias )
//
// Two kernels (fusion with grid-wide fences regressed badly in R4):
//  1) dot_kernel: 1 warp per (b,l) row, streaming states with evict-first
//     (__ldcs) so the out values stay L2-resident for kernel 2.
//  2) rcumsum_kernel: 64 blocks x 1024 threads, one float4 per thread,
//     warp suffix-scan + cross-warp scan. Latency-optimized.

static constexpr int B = 64;
static constexpr int L = 4096;
static constexpr int D = 256;          // 64 float4 per row
static constexpr int ROWS = B * L;     // 262144

__global__ void __launch_bounds__(256)
dot_kernel(const float4* __restrict__ states4,
           const float4* __restrict__ w4,
           const float*  __restrict__ bias,
           float* __restrict__ out)
{
    int gwarp = (blockIdx.x * blockDim.x + threadIdx.x) >> 5;
    int lane  = threadIdx.x & 31;

    const float4* row = states4 + (size_t)gwarp * (D / 4);

    // streaming loads, evict-first: states are touched exactly once
    float4 a0 = __ldcs(&row[lane]);
    float4 a1 = __ldcs(&row[lane + 32]);
    float4 w0 = __ldg(&w4[lane]);
    float4 w1 = __ldg(&w4[lane + 32]);

    float s = a0.x * w0.x + a0.y * w0.y + a0.z * w0.z + a0.w * w0.w
            + a1.x * w1.x + a1.y * w1.y + a1.z * w1.z + a1.w * w1.w;

    #pragma unroll
    for (int off = 16; off > 0; off >>= 1)
        s += __shfl_xor_sync(0xFFFFFFFFu, s, off);

    if (lane == 0)
        out[gwarp] = s + __ldg(bias);
}

// In-place reverse cumulative sum along L for each batch row.
// grid = B blocks, 1024 threads, each thread owns 4 contiguous elements
// (one float4). Values are L2-hot from kernel 1.
__global__ void __launch_bounds__(1024)
rcumsum_kernel(float* __restrict__ data)
{
    const int b    = blockIdx.x;
    const int t    = threadIdx.x;
    const int lane = t & 31;
    const int wid  = t >> 5;
    float* row = data + (size_t)b * L;

    float4 x = reinterpret_cast<const float4*>(row)[t];
    float v0 = x.x, v1 = x.y, v2 = x.z, v3 = x.w;
    float total = v0 + v1 + v2 + v3;

    // inclusive SUFFIX scan within warp: lane i -> sum over lanes >= i
    float s = total;
    #pragma unroll
    for (int off = 1; off < 32; off <<= 1) {
        float n = __shfl_down_sync(0xFFFFFFFFu, s, off);
        if (lane < 32 - off) s += n;
    }

    __shared__ float warp_off[32];
    {
        __shared__ float warp_tot[32];
        if (lane == 0) warp_tot[wid] = s;   // lane 0's s == warp full sum
        __syncthreads();

        if (wid == 0) {
            float ws = warp_tot[lane];
            float ss = ws;
            #pragma unroll
            for (int off = 1; off < 32; off <<= 1) {
                float n = __shfl_down_sync(0xFFFFFFFFu, ss, off);
                if (lane < 32 - off) ss += n;
            }
            warp_off[lane] = ss - ws;       // exclusive suffix of warp sums
        }
        __syncthreads();
    }

    // exclusive suffix for this thread: warps after mine + lanes after me
    float offset = warp_off[wid] + (s - total);

    // within-float4 reverse cumsum
    float q3 = offset + v3;
    float q2 = q3 + v2;
    float q1 = q2 + v1;
    float q0 = q1 + v0;

    reinterpret_cast<float4*>(row)[t] = make_float4(q0, q1, q2, q3);
}

extern "C" void kernel_launch(void* const* d_in, const int* in_sizes, int n_in,
                              void* d_out, int out_size)
{
    const float4* states4 = (const float4*)d_in[0];
    const float4* w4      = (const float4*)d_in[1];
    const float*  bias    = (const float*)d_in[2];
    float* out = (float*)d_out;

    dot_kernel<<<ROWS / 8, 256>>>(states4, w4, bias, out);
    rcumsum_kernel<<<B, 1024>>>(out);
}